// round 4
// baseline (speedup 1.0000x reference)
#include <cuda_runtime.h>
#include <math.h>

#define Nn 256
#define Ll 384
#define DMc 256
#define Hh 8
#define Dd 32
#define HD 256
#define NL (Nn*Ll)
#define LLc (Ll*Ll)
#define INV_SQRT_D 0.17677669529663687f

// ---------------- scratch (device globals; no allocation allowed) -------------
__device__ float g_qsw[Ll*HD];
__device__ float g_ksw[NL*HD];
__device__ float g_mq[NL*HD];
__device__ float g_k [NL*HD];
__device__ float g_v [NL*HD];
__device__ float g_gate[NL*HD];
__device__ float g_sw[NL*Hh];
__device__ float g_pb[Hh*LLc];
__device__ float g_attn[Hh*LLc];
__device__ float g_oatt[NL*HD];

// ---------------- helpers ----------------------------------------------------
__device__ __forceinline__ unsigned f2tf(float x){
  unsigned u; asm("cvt.rna.tf32.f32 %0, %1;" : "=r"(u) : "f"(x)); return u;
}
__device__ __forceinline__ void mma_tf32(float c[4], const unsigned a[4], const unsigned b[2]){
  asm volatile("mma.sync.aligned.m16n8k8.row.col.f32.tf32.tf32.f32 "
    "{%0,%1,%2,%3},{%4,%5,%6,%7},{%8,%9},{%0,%1,%2,%3};"
    : "+f"(c[0]),"+f"(c[1]),"+f"(c[2]),"+f"(c[3])
    : "r"(a[0]),"r"(a[1]),"r"(a[2]),"r"(a[3]),"r"(b[0]),"r"(b[1]));
}
__device__ __forceinline__ float warpSum(float v){
#pragma unroll
  for(int o=16;o;o>>=1) v += __shfl_xor_sync(0xffffffffu, v, o);
  return v;
}
__device__ __forceinline__ float warpMax(float v){
#pragma unroll
  for(int o=16;o;o>>=1) v = fmaxf(v, __shfl_xor_sync(0xffffffffu, v, o));
  return v;
}
__device__ __forceinline__ float blockSum(float v, float* red, int nw){
  int t = threadIdx.x;
  v = warpSum(v);
  if((t&31)==0) red[t>>5] = v;
  __syncthreads();
  float s = 0.f;
  if(t < 32){
    s = (t < nw) ? red[t] : 0.f;
    s = warpSum(s);
    if(t==0) red[0] = s;
  }
  __syncthreads();
  s = red[0];
  __syncthreads();
  return s;
}
__device__ __forceinline__ float blockMax(float v, float* red, int nw){
  int t = threadIdx.x;
  v = warpMax(v);
  if((t&31)==0) red[t>>5] = v;
  __syncthreads();
  float s = -3.402823e38f;
  if(t < 32){
    s = (t < nw) ? red[t] : -3.402823e38f;
    s = warpMax(s);
    if(t==0) red[0] = s;
  }
  __syncthreads();
  s = red[0];
  __syncthreads();
  return s;
}

// ---------------- K0: qsw for MSA row 0 --------------------------------------
__global__ void k_qsw(const float* __restrict__ msa,
                      const float* __restrict__ lng, const float* __restrict__ lnb,
                      const float* __restrict__ swq, const float* __restrict__ sbq){
  int i = blockIdx.x, t = threadIdx.x;
  __shared__ float sm[DMc];
  __shared__ float red[32];
  float x = msa[(size_t)i*DMc + t];          // n = 0
  float mean = blockSum(x, red, 8) * (1.f/DMc);
  float d = x - mean;
  float var = blockSum(d*d, red, 8) * (1.f/DMc);
  float m = d * rsqrtf(var + 1e-5f) * lng[t] + lnb[t];
  sm[t] = m;
  __syncthreads();
  float acc = sbq[t];
#pragma unroll 8
  for(int r=0;r<DMc;r++) acc += sm[r]*swq[r*HD + t];
  g_qsw[i*HD + t] = acc * INV_SQRT_D;
}

// ---------------- K1: LN + 5 projections via tf32 MMA ------------------------
#define PROJ_SMEM ((128*260 + 256*68 + 128+128+256+256)*4)
__global__ __launch_bounds__(512) void k_proj(
  const float* __restrict__ msa,
  const float* __restrict__ lng, const float* __restrict__ lnb,
  const float* __restrict__ w0, const float* __restrict__ w1,
  const float* __restrict__ w2, const float* __restrict__ w3,
  const float* __restrict__ w4,
  const float* __restrict__ sbk, const float* __restrict__ bg)
{
  extern __shared__ unsigned dsm[];
  unsigned (*sA)[260] = (unsigned(*)[260])dsm;               // 128 x 256 tf32
  unsigned (*sB)[68]  = (unsigned(*)[68])(dsm + 128*260);    // 256(k) x 64(n)
  float* smean = (float*)(dsm + 128*260 + 256*68);
  float* sinv  = smean + 128;
  float* sG    = sinv + 128;
  float* sBt   = sG + 256;

  const int t = threadIdx.x;
  const size_t row0 = (size_t)blockIdx.x * 128;

  if(t < 256){ sG[t] = lng[t]; sBt[t] = lnb[t]; }
  {
    int j = t>>2, q = t&3;
    const float* rp = msa + (row0 + j)*DMc + q*64;
    float s=0.f, ss=0.f;
#pragma unroll
    for(int f=0; f<16; f++){
      float4 x = *(const float4*)(rp + f*4);
      s  += x.x+x.y+x.z+x.w;
      ss += x.x*x.x + x.y*x.y + x.z*x.z + x.w*x.w;
    }
#pragma unroll
    for(int o=1;o<4;o<<=1){
      s  += __shfl_xor_sync(0xffffffffu, s, o);
      ss += __shfl_xor_sync(0xffffffffu, ss, o);
    }
    float mean = s*(1.f/256.f);
    float var  = ss*(1.f/256.f) - mean*mean;
    if(q==0){ smean[j]=mean; sinv[j]=rsqrtf(var+1e-5f); }
  }
  __syncthreads();
#pragma unroll
  for(int p=0;p<16;p++){
    int lin = p*512 + t;
    int r = lin>>6, f = lin&63;
    float4 x = *(const float4*)(msa + (row0+r)*DMc + f*4);
    float mean = smean[r], inv = sinv[r];
    int c = f*4;
    sA[r][c+0] = f2tf((x.x-mean)*inv*sG[c+0]+sBt[c+0]);
    sA[r][c+1] = f2tf((x.y-mean)*inv*sG[c+1]+sBt[c+1]);
    sA[r][c+2] = f2tf((x.z-mean)*inv*sG[c+2]+sBt[c+2]);
    sA[r][c+3] = f2tf((x.w-mean)*inv*sG[c+3]+sBt[c+3]);
  }

  const int w = t>>5, lane = t&31;
  const int wm = w>>1, wn = w&1;
  const int qr = lane>>2, ql = lane&3;

  for(int nc=0; nc<20; nc++){
    const int mi = nc>>2;
    const int off = (nc&3)*64;
    const float* W = (mi==0)?w0:(mi==1)?w1:(mi==2)?w2:(mi==3)?w3:w4;
    __syncthreads();
#pragma unroll
    for(int p=0;p<8;p++){
      int lin = p*512 + t;
      int r = lin>>4, f = lin&15;
      float4 x = *(const float4*)(W + (size_t)r*HD + off + f*4);
      int c = f*4;
      sB[r][c+0]=f2tf(x.x); sB[r][c+1]=f2tf(x.y);
      sB[r][c+2]=f2tf(x.z); sB[r][c+3]=f2tf(x.w);
    }
    __syncthreads();
    float acc[4][4];
#pragma unroll
    for(int i1=0;i1<4;i1++)
#pragma unroll
      for(int i2=0;i2<4;i2++) acc[i1][i2]=0.f;
#pragma unroll 4
    for(int ks=0; ks<32; ks++){
      int k0 = ks*8;
      unsigned a[4];
      int R = wm*16;
      a[0]=sA[R+qr  ][k0+ql  ]; a[1]=sA[R+qr+8][k0+ql  ];
      a[2]=sA[R+qr  ][k0+ql+4]; a[3]=sA[R+qr+8][k0+ql+4];
      unsigned b[4][2];
#pragma unroll
      for(int bn=0;bn<4;bn++){
        int n0 = wn*32 + bn*8;
        b[bn][0]=sB[k0+ql  ][n0+qr];
        b[bn][1]=sB[k0+ql+4][n0+qr];
      }
#pragma unroll
      for(int bn=0;bn<4;bn++) mma_tf32(acc[bn], a, b[bn]);
    }
    int rowa = (int)row0 + wm*16 + qr;
#pragma unroll
    for(int bn=0;bn<4;bn++){
      int cg = nc*64 + wn*32 + bn*8 + 2*ql;
      int c2 = cg & 255;
      size_t o0 = (size_t)rowa*HD + c2;
      size_t o1 = (size_t)(rowa+8)*HD + c2;
      float v0=acc[bn][0], v1=acc[bn][1], v2=acc[bn][2], v3=acc[bn][3];
      if(mi==0){
        float b0v = sbk[c2], b1v = sbk[c2+1];
        *(float2*)(g_ksw+o0) = make_float2(v0+b0v, v1+b1v);
        *(float2*)(g_ksw+o1) = make_float2(v2+b0v, v3+b1v);
      } else if(mi==1){
        *(float2*)(g_mq+o0) = make_float2(v0, v1);
        *(float2*)(g_mq+o1) = make_float2(v2, v3);
      } else if(mi==2){
        *(float2*)(g_k+o0) = make_float2(v0*INV_SQRT_D, v1*INV_SQRT_D);
        *(float2*)(g_k+o1) = make_float2(v2*INV_SQRT_D, v3*INV_SQRT_D);
      } else if(mi==3){
        *(float2*)(g_v+o0) = make_float2(v0, v1);
        *(float2*)(g_v+o1) = make_float2(v2, v3);
      } else {
        float b0v = bg[c2], b1v = bg[c2+1];
        *(float2*)(g_gate+o0) = make_float2(1.f/(1.f+expf(-(v0+b0v))), 1.f/(1.f+expf(-(v1+b1v))));
        *(float2*)(g_gate+o1) = make_float2(1.f/(1.f+expf(-(v2+b0v))), 1.f/(1.f+expf(-(v3+b1v))));
      }
    }
  }
}

// ---------------- K2: seq-weight logits + softmax over n ---------------------
__global__ __launch_bounds__(256) void k_swl(){
  __shared__ float sq[256];
  __shared__ float sL[256][9];
  __shared__ float smx[8], srs[8];
  int i = blockIdx.x, t = threadIdx.x;
  sq[t] = g_qsw[i*HD + t];
  __syncthreads();
  const float* kr = g_ksw + ((size_t)t*Ll + i)*HD;
  float lg[8];
#pragma unroll
  for(int h=0;h<8;h++){
    float s = 0.f;
#pragma unroll
    for(int f=0; f<8; f++){
      float4 kx = *(const float4*)(kr + h*32 + f*4);
      int c = h*32 + f*4;
      s += kx.x*sq[c] + kx.y*sq[c+1] + kx.z*sq[c+2] + kx.w*sq[c+3];
    }
    lg[h]=s; sL[t][h]=s;
  }
  __syncthreads();
  {
    int w = t>>5, lane = t&31;
    float mx = -3.402823e38f;
#pragma unroll
    for(int e=0;e<8;e++) mx = fmaxf(mx, sL[lane*8+e][w]);
    mx = warpMax(mx);
    float s = 0.f;
#pragma unroll
    for(int e=0;e<8;e++) s += expf(sL[lane*8+e][w]-mx);
    s = warpSum(s);
    if(lane==0){ smx[w]=mx; srs[w]=1.f/s; }
  }
  __syncthreads();
  size_t o = ((size_t)t*Ll + i)*Hh;
#pragma unroll
  for(int h=0;h<8;h++) g_sw[o+h] = expf(lg[h]-smx[h])*srs[h];
}

// ---------------- K3: pair LN + bias projection (warp per pair) --------------
__global__ __launch_bounds__(256) void k_pb2(const float* __restrict__ pair,
    const float* __restrict__ lnpg, const float* __restrict__ lnpb,
    const float* __restrict__ wb){
  __shared__ float swb[128*9];
  int t = threadIdx.x;
  for(int u=t; u<1024; u+=256){ swb[(u>>3)*9 + (u&7)] = wb[u]; }
  __syncthreads();
  int w = t>>5, lane = t&31;
  size_t p = (size_t)blockIdx.x*8 + w;
  const float* pr = pair + p*128;
  float4 x = *(const float4*)(pr + lane*4);
  float s  = x.x+x.y+x.z+x.w;
  float ss = x.x*x.x+x.y*x.y+x.z*x.z+x.w*x.w;
  s = warpSum(s); ss = warpSum(ss);
  float mean = s*(1.f/128.f);
  float inv = rsqrtf(ss*(1.f/128.f)-mean*mean + 1e-5f);
  int c = lane*4;
  float m0=(x.x-mean)*inv*lnpg[c+0]+lnpb[c+0];
  float m1=(x.y-mean)*inv*lnpg[c+1]+lnpb[c+1];
  float m2=(x.z-mean)*inv*lnpg[c+2]+lnpb[c+2];
  float m3=(x.w-mean)*inv*lnpg[c+3]+lnpb[c+3];
  float mine=0.f;
#pragma unroll
  for(int h=0;h<8;h++){
    float pt = m0*swb[(c+0)*9+h] + m1*swb[(c+1)*9+h]
             + m2*swb[(c+2)*9+h] + m3*swb[(c+3)*9+h];
    pt = warpSum(pt);
    if(lane==h) mine = pt;
  }
  if(lane<8) g_pb[(size_t)lane*LLc + p] = mine;
}

// ---------------- K4: attn logits via tf32 MMA -------------------------------
__global__ __launch_bounds__(256) void k_attn(){
  __shared__ unsigned sA[128][36];
  __shared__ unsigned sB[64][36];
  const int h = blockIdx.z;
  const int i0 = blockIdx.x*128, j0 = blockIdx.y*64;
  const int t = threadIdx.x, w = t>>5, lane = t&31;
  const int wm = w>>1, wn = w&1;
  const int qr = lane>>2, ql = lane&3;
  float acc[2][4][4];
#pragma unroll
  for(int am=0;am<2;am++)
#pragma unroll
    for(int bn=0;bn<4;bn++)
#pragma unroll
      for(int e=0;e<4;e++) acc[am][bn][e]=0.f;

  for(int n=0;n<Nn;n++){
    __syncthreads();
    const size_t baseA = ((size_t)n*Ll + i0)*HD + h*Dd;
#pragma unroll
    for(int p=0;p<4;p++){
      int u = p*256 + t;
      int r = u>>3, f = u&7;
      float4 x = *(const float4*)(g_mq + baseA + (size_t)r*HD + f*4);
      float sv = g_sw[((size_t)n*Ll + i0 + r)*Hh + h];
      int c = f*4;
      sA[r][c+0]=f2tf(x.x*sv); sA[r][c+1]=f2tf(x.y*sv);
      sA[r][c+2]=f2tf(x.z*sv); sA[r][c+3]=f2tf(x.w*sv);
    }
    const size_t baseB = ((size_t)n*Ll + j0)*HD + h*Dd;
#pragma unroll
    for(int p=0;p<2;p++){
      int u = p*256 + t;
      int r = u>>3, f = u&7;
      float4 x = *(const float4*)(g_k + baseB + (size_t)r*HD + f*4);
      int c = f*4;
      sB[r][c+0]=f2tf(x.x); sB[r][c+1]=f2tf(x.y);
      sB[r][c+2]=f2tf(x.z); sB[r][c+3]=f2tf(x.w);
    }
    __syncthreads();
#pragma unroll
    for(int ks=0;ks<4;ks++){
      int k0 = ks*8;
      unsigned a[2][4], b[4][2];
#pragma unroll
      for(int am=0;am<2;am++){
        int R = wm*32 + am*16;
        a[am][0]=sA[R+qr  ][k0+ql  ]; a[am][1]=sA[R+qr+8][k0+ql  ];
        a[am][2]=sA[R+qr  ][k0+ql+4]; a[am][3]=sA[R+qr+8][k0+ql+4];
      }
#pragma unroll
      for(int bn=0;bn<4;bn++){
        int n0 = wn*32 + bn*8;
        b[bn][0]=sB[n0+qr][k0+ql];
        b[bn][1]=sB[n0+qr][k0+ql+4];
      }
#pragma unroll
      for(int am=0;am<2;am++)
#pragma unroll
        for(int bn=0;bn<4;bn++) mma_tf32(acc[am][bn], a[am], b[bn]);
    }
  }
  const size_t hb = (size_t)h*LLc;
#pragma unroll
  for(int am=0;am<2;am++){
    int i = i0 + wm*32 + am*16 + qr;
#pragma unroll
    for(int bn=0;bn<4;bn++){
      int j = j0 + wn*32 + bn*8 + 2*ql;
      size_t o = hb + (size_t)i*Ll + j;
      float2 pb0 = *(const float2*)(g_pb+o);
      *(float2*)(g_attn+o) = make_float2(acc[am][bn][0]+pb0.x, acc[am][bn][1]+pb0.y);
      size_t o2 = o + (size_t)8*Ll;
      float2 pb1 = *(const float2*)(g_pb+o2);
      *(float2*)(g_attn+o2) = make_float2(acc[am][bn][2]+pb1.x, acc[am][bn][3]+pb1.y);
    }
  }
}

// ---------------- K5: softmax over j ------------------------------------------
__global__ void k_attnsoftmax(){
  int b = blockIdx.x;
  int h = b / Ll, i = b % Ll;
  int t = threadIdx.x;
  __shared__ float red[32];
  size_t base = (size_t)h*LLc + (size_t)i*Ll;
  float x0 = g_attn[base + t];
  float x1 = g_attn[base + 128 + t];
  float x2 = g_attn[base + 256 + t];
  float mx = blockMax(fmaxf(x0, fmaxf(x1,x2)), red, 4);
  float e0 = expf(x0-mx), e1 = expf(x1-mx), e2 = expf(x2-mx);
  float s = blockSum(e0+e1+e2, red, 4);
  float inv = 1.f/s;
  g_attn[base + t]       = e0*inv;
  g_attn[base + 128 + t] = e1*inv;
  g_attn[base + 256 + t] = e2*inv;
}

// ---------------- K6: P @ V via tf32 MMA -------------------------------------
__global__ __launch_bounds__(256) void k_pv(){
  __shared__ unsigned sA[128][36];
  __shared__ unsigned sB[128][36];
  const int h = blockIdx.z;
  const int i0 = blockIdx.x*128;
  const int n0 = blockIdx.y*4;
  const int t = threadIdx.x, w = t>>5, lane = t&31;
  const int wm = w>>1, wn = w&1;
  const int qr = lane>>2, ql = lane&3;
  float acc[2][8][4];
#pragma unroll
  for(int am=0;am<2;am++)
#pragma unroll
    for(int bn=0;bn<8;bn++)
#pragma unroll
      for(int e=0;e<4;e++) acc[am][bn][e]=0.f;

  const size_t attnBase = (size_t)h*LLc + (size_t)i0*Ll;
  for(int jc=0;jc<12;jc++){
    int j0 = jc*32;
    __syncthreads();
#pragma unroll
    for(int p=0;p<4;p++){
      int u = p*256 + t;
      int r = u>>3, f = u&7;
      float4 x = *(const float4*)(g_attn + attnBase + (size_t)r*Ll + j0 + f*4);
      int c = f*4;
      sA[r][c+0]=f2tf(x.x); sA[r][c+1]=f2tf(x.y);
      sA[r][c+2]=f2tf(x.z); sA[r][c+3]=f2tf(x.w);
    }
#pragma unroll
    for(int p=0;p<4;p++){
      int u = p*256 + t;
      int nv = u>>8, jj = (u>>3)&31, f = u&7;
      float4 x = *(const float4*)(g_v + ((size_t)(n0+nv)*Ll + j0+jj)*HD + h*Dd + f*4);
      int c = nv*32 + f*4;
      sB[c+0][jj]=f2tf(x.x); sB[c+1][jj]=f2tf(x.y);
      sB[c+2][jj]=f2tf(x.z); sB[c+3][jj]=f2tf(x.w);
    }
    __syncthreads();
#pragma unroll
    for(int ks=0;ks<4;ks++){
      int k0 = ks*8;
      unsigned a[2][4], b[8][2];
#pragma unroll
      for(int am=0;am<2;am++){
        int R = wm*32 + am*16;
        a[am][0]=sA[R+qr  ][k0+ql  ]; a[am][1]=sA[R+qr+8][k0+ql  ];
        a[am][2]=sA[R+qr  ][k0+ql+4]; a[am][3]=sA[R+qr+8][k0+ql+4];
      }
#pragma unroll
      for(int bn=0;bn<8;bn++){
        int nf = wn*64 + bn*8;
        b[bn][0]=sB[nf+qr][k0+ql];
        b[bn][1]=sB[nf+qr][k0+ql+4];
      }
#pragma unroll
      for(int am=0;am<2;am++)
#pragma unroll
        for(int bn=0;bn<8;bn++) mma_tf32(acc[am][bn], a[am], b[bn]);
    }
  }
#pragma unroll
  for(int am=0;am<2;am++){
    int i = i0 + wm*32 + am*16 + qr;
#pragma unroll
    for(int bn=0;bn<8;bn++){
      int col = wn*64 + bn*8 + 2*ql;
      int nv = col>>5, dd = col&31;
      size_t o = ((size_t)(n0+nv)*Ll + i)*HD + h*Dd + dd;
      *(float2*)(g_oatt+o) = make_float2(acc[am][bn][0], acc[am][bn][1]);
      size_t o2 = o + (size_t)8*HD;
      *(float2*)(g_oatt+o2) = make_float2(acc[am][bn][2], acc[am][bn][3]);
    }
  }
}

// ---------------- K7: gate + out projection via tf32 MMA ---------------------
#define OUT_SMEM ((64*260 + 256*68)*4)
__global__ __launch_bounds__(256) void k_out(const float* __restrict__ wo,
                                             const float* __restrict__ bo,
                                             float* __restrict__ out){
  extern __shared__ unsigned dsm[];
  unsigned (*sA)[260] = (unsigned(*)[260])dsm;             // 64 x 256
  unsigned (*sB)[68]  = (unsigned(*)[68])(dsm + 64*260);   // 256 x 64
  const int t = threadIdx.x;
  const size_t row0 = (size_t)blockIdx.x*64;
  const int w = t>>5, lane = t&31;
  const int wm = w>>1, wn = w&1;
  const int qr = lane>>2, ql = lane&3;
#pragma unroll
  for(int p=0;p<16;p++){
    int lin = p*256 + t;
    int r = lin>>6, f = lin&63;
    size_t o = (row0+r)*HD + f*4;
    float4 a = *(const float4*)(g_oatt + o);
    float4 g = *(const float4*)(g_gate + o);
    int c = f*4;
    sA[r][c+0]=f2tf(a.x*g.x); sA[r][c+1]=f2tf(a.y*g.y);
    sA[r][c+2]=f2tf(a.z*g.z); sA[r][c+3]=f2tf(a.w*g.w);
  }
  __syncthreads();
  for(int nc=0; nc<4; nc++){
#pragma unroll
    for(int p=0;p<16;p++){
      int lin = p*256 + t;
      int r = lin>>4, f = lin&15;
      float4 x = *(const float4*)(wo + (size_t)r*DMc + nc*64 + f*4);
      int c = f*4;
      sB[r][c+0]=f2tf(x.x); sB[r][c+1]=f2tf(x.y);
      sB[r][c+2]=f2tf(x.z); sB[r][c+3]=f2tf(x.w);
    }
    __syncthreads();
    float acc[4][4];
#pragma unroll
    for(int i1=0;i1<4;i1++)
#pragma unroll
      for(int i2=0;i2<4;i2++) acc[i1][i2]=0.f;
#pragma unroll 4
    for(int ks=0; ks<32; ks++){
      int k0 = ks*8;
      unsigned a[4];
      int R = wm*16;
      a[0]=sA[R+qr  ][k0+ql  ]; a[1]=sA[R+qr+8][k0+ql  ];
      a[2]=sA[R+qr  ][k0+ql+4]; a[3]=sA[R+qr+8][k0+ql+4];
      unsigned b[4][2];
#pragma unroll
      for(int bn=0;bn<4;bn++){
        int n0 = wn*32 + bn*8;
        b[bn][0]=sB[k0+ql  ][n0+qr];
        b[bn][1]=sB[k0+ql+4][n0+qr];
      }
#pragma unroll
      for(int bn=0;bn<4;bn++) mma_tf32(acc[bn], a, b[bn]);
    }
    int rowa = (int)row0 + wm*16 + qr;
#pragma unroll
    for(int bn=0;bn<4;bn++){
      int cg = nc*64 + wn*32 + bn*8 + 2*ql;
      float2 b2 = *(const float2*)(bo + cg);
      *(float2*)(out + (size_t)rowa*DMc + cg) =
          make_float2(acc[bn][0]+b2.x, acc[bn][1]+b2.y);
      *(float2*)(out + (size_t)(rowa+8)*DMc + cg) =
          make_float2(acc[bn][2]+b2.x, acc[bn][3]+b2.y);
    }
    __syncthreads();
  }
}

// ---------------- launch -----------------------------------------------------
extern "C" void kernel_launch(void* const* d_in, const int* in_sizes, int n_in,
                              void* d_out, int out_size){
  const float* msa      = (const float*)d_in[0];
  const float* pair     = (const float*)d_in[1];
  const float* ln_msa_g = (const float*)d_in[2];
  const float* ln_msa_b = (const float*)d_in[3];
  const float* ln_pair_g= (const float*)d_in[4];
  const float* ln_pair_b= (const float*)d_in[5];
  const float* sw_wq    = (const float*)d_in[6];
  const float* sw_bq    = (const float*)d_in[7];
  const float* sw_wk    = (const float*)d_in[8];
  const float* sw_bk    = (const float*)d_in[9];
  const float* wq       = (const float*)d_in[10];
  const float* wk       = (const float*)d_in[11];
  const float* wv       = (const float*)d_in[12];
  const float* wb       = (const float*)d_in[13];
  const float* wg       = (const float*)d_in[14];
  const float* bg       = (const float*)d_in[15];
  const float* wo       = (const float*)d_in[16];
  const float* bo       = (const float*)d_in[17];
  float* out = (float*)d_out;

  cudaFuncSetAttribute(k_proj, cudaFuncAttributeMaxDynamicSharedMemorySize, PROJ_SMEM);
  cudaFuncSetAttribute(k_out,  cudaFuncAttributeMaxDynamicSharedMemorySize, OUT_SMEM);

  k_qsw<<<Ll, 256>>>(msa, ln_msa_g, ln_msa_b, sw_wq, sw_bq);
  k_proj<<<NL/128, 512, PROJ_SMEM>>>(msa, ln_msa_g, ln_msa_b,
                                     sw_wk, wq, wk, wv, wg, sw_bk, bg);
  k_swl<<<Ll, 256>>>();
  k_pb2<<<LLc/8, 256>>>(pair, ln_pair_g, ln_pair_b, wb);
  k_attn<<<dim3(3,6,8), 256>>>();
  k_attnsoftmax<<<Hh*Ll, 128>>>();
  k_pv<<<dim3(3,64,8), 256>>>();   // 256 n-rows / 4 per block = 64
  k_out<<<NL/64, 256, OUT_SMEM>>>(wo, bo, out);
}

// round 6
// speedup vs baseline: 1.6121x; 1.6121x over previous
#include <cuda_runtime.h>
#include <math.h>
#include <stdint.h>

#define Nn 256
#define Ll 384
#define Hh 8
#define Dd 32
#define HD 256
#define NL (Nn*Ll)
#define LLc (Ll*Ll)
#define ISD 0.17677669529663687f

// fp32 scratch
__device__ float g_qsw[Ll*HD];
__device__ float g_ksw[NL*HD];
__device__ float g_mq[NL*HD];
__device__ float g_gate[NL*HD];
__device__ float g_sw[NL*Hh];
__device__ float g_pb[Hh*LLc];
__device__ float g_attn[Hh*LLc];
__device__ float g_oatt[NL*HD];
// tf32-preconverted operands
__device__ unsigned g_wt[6*256*256];   // [mat][n][k]
__device__ unsigned g_kt[NL*HD];       // K * 1/sqrt(D)
__device__ unsigned g_qst[NL*HD];      // Q * seqweight
__device__ unsigned g_pt[Hh*LLc];      // softmax probs
__device__ unsigned g_vT[NL*HD];       // V transposed: [(n*8+h)*32+d][i]

// ---------------- helpers ----------------------------------------------------
__device__ __forceinline__ unsigned f2tf(float x){
  unsigned u; asm("cvt.rna.tf32.f32 %0, %1;" : "=r"(u) : "f"(x)); return u;
}
__device__ __forceinline__ void mma_tf32(float c[4], const unsigned a[4], const unsigned b[2]){
  asm volatile("mma.sync.aligned.m16n8k8.row.col.f32.tf32.tf32.f32 "
    "{%0,%1,%2,%3},{%4,%5,%6,%7},{%8,%9},{%0,%1,%2,%3};"
    : "+f"(c[0]),"+f"(c[1]),"+f"(c[2]),"+f"(c[3])
    : "r"(a[0]),"r"(a[1]),"r"(a[2]),"r"(a[3]),"r"(b[0]),"r"(b[1]));
}
__device__ __forceinline__ uint32_t s2u(const void* p){
  uint32_t a; asm("{ .reg .u64 t; cvta.to.shared.u64 t, %1; cvt.u32.u64 %0, t; }" : "=r"(a) : "l"(p)); return a;
}
__device__ __forceinline__ void cpa16(uint32_t s, const void* g){
  asm volatile("cp.async.cg.shared.global [%0], [%1], 16;" :: "r"(s), "l"(g));
}
#define CPC() asm volatile("cp.async.commit_group;" ::: "memory")
#define CPW1() asm volatile("cp.async.wait_group 1;" ::: "memory")
#define CPW0() asm volatile("cp.async.wait_group 0;" ::: "memory")

__device__ __forceinline__ float warpSum(float v){
#pragma unroll
  for(int o=16;o;o>>=1) v += __shfl_xor_sync(0xffffffffu, v, o);
  return v;
}
__device__ __forceinline__ float warpMax(float v){
#pragma unroll
  for(int o=16;o;o>>=1) v = fmaxf(v, __shfl_xor_sync(0xffffffffu, v, o));
  return v;
}
__device__ __forceinline__ float blockSum(float v, float* red, int nw){
  int t=threadIdx.x; v=warpSum(v);
  if((t&31)==0) red[t>>5]=v;
  __syncthreads();
  float s=0.f;
  if(t<32){ s=(t<nw)?red[t]:0.f; s=warpSum(s); if(t==0) red[0]=s; }
  __syncthreads(); s=red[0]; __syncthreads(); return s;
}
__device__ __forceinline__ float blockMax(float v, float* red, int nw){
  int t=threadIdx.x; v=warpMax(v);
  if((t&31)==0) red[t>>5]=v;
  __syncthreads();
  float s=-3.4e38f;
  if(t<32){ s=(t<nw)?red[t]:-3.4e38f; s=warpMax(s); if(t==0) red[0]=s; }
  __syncthreads(); s=red[0]; __syncthreads(); return s;
}

// ---- prep: convert+transpose 6 weight mats to tf32 [mat][n][k] ---------------
__global__ void k_prep(const float* __restrict__ w0, const float* __restrict__ w1,
                       const float* __restrict__ w2, const float* __restrict__ w3,
                       const float* __restrict__ w4, const float* __restrict__ w5){
  int bid = blockIdx.x, t = threadIdx.x;
  int mat = bid>>8, n = bid&255;
  const float* W = (mat==0)?w0:(mat==1)?w1:(mat==2)?w2:(mat==3)?w3:(mat==4)?w4:w5;
  g_wt[(size_t)bid*256 + t] = f2tf(W[t*256 + n]);
}

// ---- K0: qsw row 0 -----------------------------------------------------------
__global__ void k_qsw(const float* __restrict__ msa, const float* __restrict__ lng,
                      const float* __restrict__ lnb, const float* __restrict__ swq,
                      const float* __restrict__ sbq){
  int i = blockIdx.x, t = threadIdx.x;
  __shared__ float sm[HD]; __shared__ float red[32];
  float x = msa[(size_t)i*HD + t];
  float mean = blockSum(x, red, 8)*(1.f/HD);
  float d = x-mean;
  float var = blockSum(d*d, red, 8)*(1.f/HD);
  sm[t] = d*rsqrtf(var+1e-5f)*lng[t]+lnb[t];
  __syncthreads();
  float acc = sbq[t];
#pragma unroll 8
  for(int r=0;r<HD;r++) acc += sm[r]*swq[r*HD+t];
  g_qsw[i*HD+t] = acc*ISD;
}

// ---- K3: pair LN + bias proj (launch position 3) -----------------------------
__global__ __launch_bounds__(256) void k_pb2(const float* __restrict__ pair,
    const float* __restrict__ lnpg, const float* __restrict__ lnpb,
    const float* __restrict__ wb){
  __shared__ float swb[128*9];
  int t = threadIdx.x;
  for(int u=t; u<1024; u+=256) swb[(u>>3)*9 + (u&7)] = wb[u];
  __syncthreads();
  int w=t>>5, lane=t&31;
  size_t p = (size_t)blockIdx.x*8 + w;
  float4 x = *(const float4*)(pair + p*128 + lane*4);
  float s = x.x+x.y+x.z+x.w;
  float ss = x.x*x.x+x.y*x.y+x.z*x.z+x.w*x.w;
  s=warpSum(s); ss=warpSum(ss);
  float mean = s*(1.f/128.f);
  float inv = rsqrtf(ss*(1.f/128.f)-mean*mean+1e-5f);
  int c = lane*4;
  float m0=(x.x-mean)*inv*lnpg[c]+lnpb[c],     m1=(x.y-mean)*inv*lnpg[c+1]+lnpb[c+1];
  float m2=(x.z-mean)*inv*lnpg[c+2]+lnpb[c+2], m3=(x.w-mean)*inv*lnpg[c+3]+lnpb[c+3];
  float mine=0.f;
#pragma unroll
  for(int h=0;h<8;h++){
    float pt = m0*swb[c*9+h]+m1*swb[(c+1)*9+h]+m2*swb[(c+2)*9+h]+m3*swb[(c+3)*9+h];
    pt = warpSum(pt);
    if(lane==h) mine = pt;
  }
  if(lane<8) g_pb[(size_t)lane*LLc + p] = mine;
}

// ---- K1: LN + 5 projections, cp.async double-buffered B ----------------------
// smem: A 128x260 tf32; B 2 x (64 n x 132-pad k-words)
#define PROJ_SMEM ((128*260 + 2*64*132)*4)
__global__ __launch_bounds__(512) void k_proj(const float* __restrict__ msa,
    const float* __restrict__ lng, const float* __restrict__ lnb,
    const float* __restrict__ sbk, const float* __restrict__ bg){
  extern __shared__ unsigned dsm[];
  unsigned (*sA)[260] = (unsigned(*)[260])dsm;
  unsigned* sB = dsm + 128*260;
  const uint32_t sbB = s2u(sB);
  __shared__ float smean[128], sinv[128];

  const int t = threadIdx.x;
  const size_t row0 = (size_t)blockIdx.x*128;
  const int nn = (int)(row0/Ll);           // blocks never straddle an n boundary
  const int ibase = (int)(row0%Ll);

  // prefetch tile 0 (mat0, sub0, kh0)
  {
#pragma unroll
    for(int c=0;c<4;c++){
      int u = c*512 + t, n = u>>5, cu = u&31;
      cpa16(sbB + (n*132 + cu*4)*4, &g_wt[(size_t)n*256 + cu*4]);
    }
    CPC();
  }
  // LN stats: 4 threads/row
  {
    int j = t>>2, q = t&3;
    const float* rp = msa + (row0+j)*HD + q*64;
    float s=0.f, ss=0.f;
#pragma unroll
    for(int f=0;f<16;f++){ float4 x = *(const float4*)(rp+f*4);
      s += x.x+x.y+x.z+x.w; ss += x.x*x.x+x.y*x.y+x.z*x.z+x.w*x.w; }
#pragma unroll
    for(int o=1;o<4;o<<=1){ s += __shfl_xor_sync(0xffffffffu,s,o); ss += __shfl_xor_sync(0xffffffffu,ss,o); }
    float mean = s*(1.f/HD), var = ss*(1.f/HD)-mean*mean;
    if(q==0){ smean[j]=mean; sinv[j]=rsqrtf(var+1e-5f); }
  }
  __syncthreads();
  // build A (LN + cvt.rna)
#pragma unroll
  for(int p=0;p<16;p++){
    int lin = p*512 + t, r = lin>>6, f = lin&63;
    float4 x = *(const float4*)(msa + (row0+r)*HD + f*4);
    float mean = smean[r], inv = sinv[r];
    int c = f*4;
    sA[r][c  ] = f2tf((x.x-mean)*inv*lng[c  ]+lnb[c  ]);
    sA[r][c+1] = f2tf((x.y-mean)*inv*lng[c+1]+lnb[c+1]);
    sA[r][c+2] = f2tf((x.z-mean)*inv*lng[c+2]+lnb[c+2]);
    sA[r][c+3] = f2tf((x.w-mean)*inv*lng[c+3]+lnb[c+3]);
  }

  const int w = t>>5, lane = t&31;
  const int wm = w>>1, wn = w&1;
  const int qr = lane>>2, ql = lane&3;
  float acc[4][4];

  for(int T=0; T<40; T++){
    const int nc = T>>1, kh = T&1, mi = nc>>2, sub = nc&3;
    if(T+1 < 40){
      int nc2 = (T+1)>>1, kh2 = (T+1)&1;
      const unsigned* src = g_wt + (size_t)(((nc2>>2)*256 + (nc2&3)*64)<<8) + kh2*128;
      uint32_t dst = sbB + (((T+1)&1)*8448)*4;
#pragma unroll
      for(int c=0;c<4;c++){
        int u = c*512 + t, n = u>>5, cu = u&31;
        cpa16(dst + (n*132 + cu*4)*4, src + ((size_t)n<<8) + cu*4);
      }
      CPC(); CPW1();
    } else CPW0();
    __syncthreads();

    if(kh==0){
#pragma unroll
      for(int i1=0;i1<4;i1++)
#pragma unroll
        for(int i2=0;i2<4;i2++) acc[i1][i2]=0.f;
    }
    const unsigned* bufW = sB + (T&1)*8448;
#pragma unroll 4
    for(int ks=0; ks<16; ks++){
      int kA = kh*128 + ks*8, kB = ks*8;
      unsigned a[4];
      int R = wm*16;
      a[0]=sA[R+qr  ][kA+ql  ]; a[1]=sA[R+qr+8][kA+ql  ];
      a[2]=sA[R+qr  ][kA+ql+4]; a[3]=sA[R+qr+8][kA+ql+4];
      unsigned b[4][2];
#pragma unroll
      for(int bn=0;bn<4;bn++){
        const unsigned* bp = bufW + (wn*32+bn*8+qr)*132 + kB;
        b[bn][0]=bp[ql]; b[bn][1]=bp[ql+4];
      }
#pragma unroll
      for(int bn=0;bn<4;bn++) mma_tf32(acc[bn], a, b[bn]);
    }
    if(kh==1){
      int rloc = wm*16 + qr;
      int rowa = (int)row0 + rloc;
#pragma unroll
      for(int bn=0;bn<4;bn++){
        int cg = sub*64 + wn*32 + bn*8 + 2*ql;
        size_t o0 = (size_t)rowa*HD + cg, o1 = o0 + 8*HD;
        float v0=acc[bn][0], v1=acc[bn][1], v2=acc[bn][2], v3=acc[bn][3];
        if(mi==0){
          float b0=sbk[cg], b1=sbk[cg+1];
          *(float2*)(g_ksw+o0)=make_float2(v0+b0,v1+b1);
          *(float2*)(g_ksw+o1)=make_float2(v2+b0,v3+b1);
        } else if(mi==1){
          *(float2*)(g_mq+o0)=make_float2(v0,v1);
          *(float2*)(g_mq+o1)=make_float2(v2,v3);
        } else if(mi==2){
          uint2 u0 = make_uint2(f2tf(v0*ISD), f2tf(v1*ISD));
          uint2 u1 = make_uint2(f2tf(v2*ISD), f2tf(v3*ISD));
          *(uint2*)(g_kt+o0)=u0; *(uint2*)(g_kt+o1)=u1;
        } else if(mi==3){
          int i = ibase + rloc;
          size_t d0 = ((size_t)(nn*8 + (cg>>5))*32 + (cg&31))*Ll + i;
          g_vT[d0]      = f2tf(v0);
          g_vT[d0+Ll]   = f2tf(v1);
          g_vT[d0+8]    = f2tf(v2);
          g_vT[d0+Ll+8] = f2tf(v3);
        } else {
          float b0=bg[cg], b1=bg[cg+1];
          *(float2*)(g_gate+o0)=make_float2(1.f/(1.f+expf(-(v0+b0))), 1.f/(1.f+expf(-(v1+b1))));
          *(float2*)(g_gate+o1)=make_float2(1.f/(1.f+expf(-(v2+b0))), 1.f/(1.f+expf(-(v3+b1))));
        }
      }
    }
    __syncthreads();
  }
}

// ---- K2: seq-weight logits + softmax over n ----------------------------------
__global__ __launch_bounds__(256) void k_swl(){
  __shared__ float sq[256]; __shared__ float sL[256][9];
  __shared__ float smx[8], srs[8];
  int i = blockIdx.x, t = threadIdx.x;
  sq[t] = g_qsw[i*HD+t];
  __syncthreads();
  const float* kr = g_ksw + ((size_t)t*Ll + i)*HD;
  float lg[8];
#pragma unroll
  for(int h=0;h<8;h++){
    float s=0.f;
#pragma unroll
    for(int f=0;f<8;f++){
      float4 kx = *(const float4*)(kr + h*32 + f*4);
      int c = h*32+f*4;
      s += kx.x*sq[c]+kx.y*sq[c+1]+kx.z*sq[c+2]+kx.w*sq[c+3];
    }
    lg[h]=s; sL[t][h]=s;
  }
  __syncthreads();
  { int w=t>>5, lane=t&31;
    float mx=-3.4e38f;
#pragma unroll
    for(int e=0;e<8;e++) mx=fmaxf(mx, sL[lane*8+e][w]);
    mx=warpMax(mx);
    float s=0.f;
#pragma unroll
    for(int e=0;e<8;e++) s+=expf(sL[lane*8+e][w]-mx);
    s=warpSum(s);
    if(lane==0){ smx[w]=mx; srs[w]=1.f/s; } }
  __syncthreads();
  size_t o = ((size_t)t*Ll + i)*Hh;
#pragma unroll
  for(int h=0;h<8;h++) g_sw[o+h] = expf(lg[h]-smx[h])*srs[h];
}

// ---- K_qs: Q * seqweight -> tf32 ---------------------------------------------
__global__ __launch_bounds__(256) void k_qs(){
  int u = blockIdx.x*256 + threadIdx.x;
  int row = u>>6, c4 = (u&63)*4;
  float sv = g_sw[(size_t)row*Hh + (c4>>5)];
  float4 x = *(const float4*)(g_mq + (size_t)row*HD + c4);
  uint4 o;
  o.x=f2tf(x.x*sv); o.y=f2tf(x.y*sv); o.z=f2tf(x.z*sv); o.w=f2tf(x.w*sv);
  *(uint4*)(g_qst + (size_t)row*HD + c4) = o;
}

// ---- K4: attn logits, cp.async double-buffered --------------------------------
// buffer: A 128x36 + B 64x36 words = 6912 words per stage, x2
#define ATTN_SMEM (2*6912*4)
__global__ __launch_bounds__(256) void k_attn(){
  extern __shared__ unsigned dsm[];
  const uint32_t sb = s2u(dsm);
  const int t = threadIdx.x, h = blockIdx.z, i0 = blockIdx.x*128, j0 = blockIdx.y*64;
  const int w = t>>5, lane = t&31;
  const int wm = w>>1, wn = w&1;
  const int qr = lane>>2, ql = lane&3;
  float acc[2][4][4];
#pragma unroll
  for(int am=0;am<2;am++)
#pragma unroll
    for(int bn=0;bn<4;bn++)
#pragma unroll
      for(int e=0;e<4;e++) acc[am][bn][e]=0.f;

  // prefetch n=0
  {
#pragma unroll
    for(int c=0;c<4;c++){ int u=c*256+t, r=u>>3, cu=u&7;
      cpa16(sb + (r*36+cu*4)*4, &g_qst[((size_t)(i0+r))*HD + h*32 + cu*4]); }
#pragma unroll
    for(int c=0;c<2;c++){ int u=c*256+t, r=u>>3, cu=u&7;
      cpa16(sb + (4608+r*36+cu*4)*4, &g_kt[((size_t)(j0+r))*HD + h*32 + cu*4]); }
    CPC();
  }
  for(int n=0;n<Nn;n++){
    if(n+1<Nn){
      uint32_t dst = sb + (((n+1)&1)*6912)*4;
      size_t rowA = (size_t)(n+1)*Ll + i0, rowB = (size_t)(n+1)*Ll + j0;
#pragma unroll
      for(int c=0;c<4;c++){ int u=c*256+t, r=u>>3, cu=u&7;
        cpa16(dst + (r*36+cu*4)*4, &g_qst[(rowA+r)*HD + h*32 + cu*4]); }
#pragma unroll
      for(int c=0;c<2;c++){ int u=c*256+t, r=u>>3, cu=u&7;
        cpa16(dst + (4608+r*36+cu*4)*4, &g_kt[(rowB+r)*HD + h*32 + cu*4]); }
      CPC(); CPW1();
    } else CPW0();
    __syncthreads();
    const unsigned* A = dsm + (n&1)*6912;
    const unsigned* B = A + 4608;
#pragma unroll
    for(int ks=0;ks<4;ks++){
      int k0 = ks*8;
      unsigned a[2][4], b[4][2];
#pragma unroll
      for(int am=0;am<2;am++){
        int R = wm*32 + am*16;
        a[am][0]=A[(R+qr  )*36+k0+ql  ]; a[am][1]=A[(R+qr+8)*36+k0+ql  ];
        a[am][2]=A[(R+qr  )*36+k0+ql+4]; a[am][3]=A[(R+qr+8)*36+k0+ql+4];
      }
#pragma unroll
      for(int bn=0;bn<4;bn++){
        const unsigned* bp = B + (wn*32+bn*8+qr)*36 + k0;
        b[bn][0]=bp[ql]; b[bn][1]=bp[ql+4];
      }
#pragma unroll
      for(int am=0;am<2;am++)
#pragma unroll
        for(int bn=0;bn<4;bn++) mma_tf32(acc[am][bn], a[am], b[bn]);
    }
    __syncthreads();
  }
  const size_t hb = (size_t)h*LLc;
#pragma unroll
  for(int am=0;am<2;am++){
    int i = i0 + wm*32 + am*16 + qr;
#pragma unroll
    for(int bn=0;bn<4;bn++){
      int j = j0 + wn*32 + bn*8 + 2*ql;
      size_t o = hb + (size_t)i*Ll + j;
      float2 pb0 = *(const float2*)(g_pb+o);
      *(float2*)(g_attn+o) = make_float2(acc[am][bn][0]+pb0.x, acc[am][bn][1]+pb0.y);
      size_t o2 = o + (size_t)8*Ll;
      float2 pb1 = *(const float2*)(g_pb+o2);
      *(float2*)(g_attn+o2) = make_float2(acc[am][bn][2]+pb1.x, acc[am][bn][3]+pb1.y);
    }
  }
}

// ---- K5: softmax over j -> tf32 probs ----------------------------------------
__global__ void k_attnsoftmax(){
  int b = blockIdx.x, h = b/Ll, i = b%Ll, t = threadIdx.x;
  __shared__ float red[32];
  size_t base = (size_t)h*LLc + (size_t)i*Ll;
  float x0 = g_attn[base+t], x1 = g_attn[base+128+t], x2 = g_attn[base+256+t];
  float mx = blockMax(fmaxf(x0,fmaxf(x1,x2)), red, 4);
  float e0=expf(x0-mx), e1=expf(x1-mx), e2=expf(x2-mx);
  float s = blockSum(e0+e1+e2, red, 4);
  float inv = 1.f/s;
  g_pt[base+t]     = f2tf(e0*inv);
  g_pt[base+128+t] = f2tf(e1*inv);
  g_pt[base+256+t] = f2tf(e2*inv);
}

// ---- K6: P @ V, cp.async double-buffered -------------------------------------
// buffer: A 128x36 + B 128x36 = 9216 words per stage, x2
#define PV_SMEM (2*9216*4)
__global__ __launch_bounds__(256) void k_pv(){
  extern __shared__ unsigned dsm[];
  const uint32_t sb = s2u(dsm);
  const int t = threadIdx.x, h = blockIdx.z, i0 = blockIdx.x*128, n0 = blockIdx.y*4;
  const int w = t>>5, lane = t&31;
  const int wm = w>>1, wn = w&1;
  const int qr = lane>>2, ql = lane&3;
  float acc[2][8][4];
#pragma unroll
  for(int am=0;am<2;am++)
#pragma unroll
    for(int bn=0;bn<8;bn++)
#pragma unroll
      for(int e=0;e<4;e++) acc[am][bn][e]=0.f;

  const size_t aBase = (size_t)h*LLc + (size_t)i0*Ll;
  // prefetch jc=0
  {
#pragma unroll
    for(int c=0;c<4;c++){ int u=c*256+t, r=u>>3, cu=u&7;
      cpa16(sb + (r*36+cu*4)*4, &g_pt[aBase + (size_t)r*Ll + cu*4]); }
#pragma unroll
    for(int c=0;c<4;c++){ int u=c*256+t, rr=u>>3, cu=u&7;
      size_t grow = ((size_t)(n0+(rr>>5))*8 + h)*32 + (rr&31);
      cpa16(sb + (4608+rr*36+cu*4)*4, &g_vT[grow*Ll + cu*4]); }
    CPC();
  }
  for(int jc=0;jc<12;jc++){
    if(jc+1<12){
      int j1 = (jc+1)*32;
      uint32_t dst = sb + (((jc+1)&1)*9216)*4;
#pragma unroll
      for(int c=0;c<4;c++){ int u=c*256+t, r=u>>3, cu=u&7;
        cpa16(dst + (r*36+cu*4)*4, &g_pt[aBase + (size_t)r*Ll + j1 + cu*4]); }
#pragma unroll
      for(int c=0;c<4;c++){ int u=c*256+t, rr=u>>3, cu=u&7;
        size_t grow = ((size_t)(n0+(rr>>5))*8 + h)*32 + (rr&31);
        cpa16(dst + (4608+rr*36+cu*4)*4, &g_vT[grow*Ll + j1 + cu*4]); }
      CPC(); CPW1();
    } else CPW0();
    __syncthreads();
    const unsigned* A = dsm + (jc&1)*9216;
    const unsigned* B = A + 4608;
#pragma unroll
    for(int ks=0;ks<4;ks++){
      int k0 = ks*8;
      unsigned a[2][4], b[8][2];
#pragma unroll
      for(int am=0;am<2;am++){
        int R = wm*32 + am*16;
        a[am][0]=A[(R+qr  )*36+k0+ql  ]; a[am][1]=A[(R+qr+8)*36+k0+ql  ];
        a[am][2]=A[(R+qr  )*36+k0+ql+4]; a[am][3]=A[(R+qr+8)*36+k0+ql+4];
      }
#pragma unroll
      for(int bn=0;bn<8;bn++){
        const unsigned* bp = B + (wn*64+bn*8+qr)*36 + k0;
        b[bn][0]=bp[ql]; b[bn][1]=bp[ql+4];
      }
#pragma unroll
      for(int am=0;am<2;am++)
#pragma unroll
        for(int bn=0;bn<8;bn++) mma_tf32(acc[am][bn], a[am], b[bn]);
    }
    __syncthreads();
  }
#pragma unroll
  for(int am=0;am<2;am++){
    int i = i0 + wm*32 + am*16 + qr;
#pragma unroll
    for(int bn=0;bn<8;bn++){
      int col = wn*64 + bn*8 + 2*ql;
      int nv = col>>5, dd = col&31;
      size_t o = ((size_t)(n0+nv)*Ll + i)*HD + h*Dd + dd;
      *(float2*)(g_oatt+o) = make_float2(acc[am][bn][0], acc[am][bn][1]);
      size_t o2 = o + (size_t)8*HD;
      *(float2*)(g_oatt+o2) = make_float2(acc[am][bn][2], acc[am][bn][3]);
    }
  }
}

// ---- K7: gate + out projection, cp.async double-buffered B -------------------
#define OUT_SMEM ((64*260 + 2*64*132)*4)
__global__ __launch_bounds__(256) void k_out(const float* __restrict__ bo,
                                             float* __restrict__ out){
  extern __shared__ unsigned dsm[];
  unsigned (*sA)[260] = (unsigned(*)[260])dsm;
  unsigned* sB = dsm + 64*260;
  const uint32_t sbB = s2u(sB);
  const int t = threadIdx.x;
  const size_t row0 = (size_t)blockIdx.x*64;
  const int w = t>>5, lane = t&31;
  const int wm = w>>1, wn = w&1;
  const int qr = lane>>2, ql = lane&3;

  // prefetch tile 0 (nc0, kh0) of wo (mat 5)
  {
#pragma unroll
    for(int c=0;c<8;c++){
      int u = c*256 + t, n = u>>5, cu = u&31;
      cpa16(sbB + (n*132 + cu*4)*4, &g_wt[(size_t)(5*256 + n)*256 + cu*4]);
    }
    CPC();
  }
  // A = oatt*gate
#pragma unroll
  for(int p=0;p<16;p++){
    int lin = p*256 + t, r = lin>>6, f = lin&63;
    size_t o = (row0+r)*HD + f*4;
    float4 a = *(const float4*)(g_oatt+o);
    float4 g = *(const float4*)(g_gate+o);
    int c = f*4;
    sA[r][c]=f2tf(a.x*g.x); sA[r][c+1]=f2tf(a.y*g.y);
    sA[r][c+2]=f2tf(a.z*g.z); sA[r][c+3]=f2tf(a.w*g.w);
  }
  float acc[4][4];
  for(int T=0;T<8;T++){
    const int nc = T>>1, kh = T&1;
    if(T+1<8){
      int nc2=(T+1)>>1, kh2=(T+1)&1;
      const unsigned* src = g_wt + (size_t)(5*256 + nc2*64)*256 + kh2*128;
      uint32_t dst = sbB + (((T+1)&1)*8448)*4;
#pragma unroll
      for(int c=0;c<8;c++){
        int u = c*256 + t, n = u>>5, cu = u&31;
        cpa16(dst + (n*132 + cu*4)*4, src + ((size_t)n<<8) + cu*4);
      }
      CPC(); CPW1();
    } else CPW0();
    __syncthreads();
    if(kh==0){
#pragma unroll
      for(int i1=0;i1<4;i1++)
#pragma unroll
        for(int i2=0;i2<4;i2++) acc[i1][i2]=0.f;
    }
    const unsigned* bufW = sB + (T&1)*8448;
#pragma unroll 4
    for(int ks=0;ks<16;ks++){
      int kA = kh*128 + ks*8, kB = ks*8;
      unsigned a[4];
      int R = wm*16;
      a[0]=sA[R+qr  ][kA+ql  ]; a[1]=sA[R+qr+8][kA+ql  ];
      a[2]=sA[R+qr  ][kA+ql+4]; a[3]=sA[R+qr+8][kA+ql+4];
      unsigned b[4][2];
#pragma unroll
      for(int bn=0;bn<4;bn++){
        const unsigned* bp = bufW + (wn*32+bn*8+qr)*132 + kB;
        b[bn][0]=bp[ql]; b[bn][1]=bp[ql+4];
      }
#pragma unroll
      for(int bn=0;bn<4;bn++) mma_tf32(acc[bn], a, b[bn]);
    }
    if(kh==1){
      int rowa = (int)row0 + wm*16 + qr;
#pragma unroll
      for(int bn=0;bn<4;bn++){
        int cg = nc*64 + wn*32 + bn*8 + 2*ql;
        float2 b2 = *(const float2*)(bo + cg);
        *(float2*)(out + (size_t)rowa*HD + cg) = make_float2(acc[bn][0]+b2.x, acc[bn][1]+b2.y);
        *(float2*)(out + (size_t)(rowa+8)*HD + cg) = make_float2(acc[bn][2]+b2.x, acc[bn][3]+b2.y);
      }
    }
    __syncthreads();
  }
}

// ---- launch ------------------------------------------------------------------
extern "C" void kernel_launch(void* const* d_in, const int* in_sizes, int n_in,
                              void* d_out, int out_size){
  const float* msa      = (const float*)d_in[0];
  const float* pair     = (const float*)d_in[1];
  const float* ln_msa_g = (const float*)d_in[2];
  const float* ln_msa_b = (const float*)d_in[3];
  const float* ln_pair_g= (const float*)d_in[4];
  const float* ln_pair_b= (const float*)d_in[5];
  const float* sw_wq    = (const float*)d_in[6];
  const float* sw_bq    = (const float*)d_in[7];
  const float* sw_wk    = (const float*)d_in[8];
  const float* sw_bk    = (const float*)d_in[9];
  const float* wq       = (const float*)d_in[10];
  const float* wk       = (const float*)d_in[11];
  const float* wv       = (const float*)d_in[12];
  const float* wb       = (const float*)d_in[13];
  const float* wg       = (const float*)d_in[14];
  const float* bg       = (const float*)d_in[15];
  const float* wo       = (const float*)d_in[16];
  const float* bo       = (const float*)d_in[17];
  float* out = (float*)d_out;

  cudaFuncSetAttribute(k_proj, cudaFuncAttributeMaxDynamicSharedMemorySize, PROJ_SMEM);
  cudaFuncSetAttribute(k_attn, cudaFuncAttributeMaxDynamicSharedMemorySize, ATTN_SMEM);
  cudaFuncSetAttribute(k_pv,   cudaFuncAttributeMaxDynamicSharedMemorySize, PV_SMEM);
  cudaFuncSetAttribute(k_out,  cudaFuncAttributeMaxDynamicSharedMemorySize, OUT_SMEM);

  k_prep<<<6*256, 256>>>(sw_wk, wq, wk, wv, wg, wo);          // 1
  k_qsw<<<Ll, 256>>>(msa, ln_msa_g, ln_msa_b, sw_wq, sw_bq);  // 2
  k_pb2<<<LLc/8, 256>>>(pair, ln_pair_g, ln_pair_b, wb);      // 3
  k_proj<<<NL/128, 512, PROJ_SMEM>>>(msa, ln_msa_g, ln_msa_b, sw_bk, bg); // 4 (ncu slot)
  k_swl<<<Ll, 256>>>();                                       // 5
  k_qs<<<NL*HD/1024, 256>>>();                                // 6
  k_attn<<<dim3(3,6,8), 256, ATTN_SMEM>>>();                  // 7
  k_attnsoftmax<<<Hh*Ll, 128>>>();                            // 8
  k_pv<<<dim3(3,64,8), 256, PV_SMEM>>>();                     // 9
  k_out<<<NL/64, 256, OUT_SMEM>>>(bo, out);                   // 10
}

// round 7
// speedup vs baseline: 2.0819x; 1.2914x over previous
#include <cuda_runtime.h>
#include <math.h>
#include <stdint.h>

#define Nn 256
#define Ll 384
#define Hh 8
#define Dd 32
#define HD 256
#define NL (Nn*Ll)
#define LLc (Ll*Ll)
#define ISD 0.17677669529663687f

// fp32 scratch
__device__ float g_qsw[Ll*HD];
__device__ float g_ksw[NL*HD];
__device__ float g_mq[NL*HD];
__device__ float g_gate[NL*HD];
__device__ float g_sw[NL*Hh];
__device__ float g_pb[Hh*LLc];
__device__ float g_attn[Hh*LLc];
__device__ float g_oatt[NL*HD];
// tf32-preconverted operands
__device__ unsigned g_wt[6*256*256];   // [mat][n][k]
__device__ unsigned g_kt[NL*HD];       // K * 1/sqrt(D)
__device__ unsigned g_qst[NL*HD];      // Q * seqweight
__device__ unsigned g_pt[Hh*LLc];      // softmax probs
__device__ unsigned g_vT[NL*HD];       // V transposed: [(n*8+h)*32+d][i]

// ---------------- helpers ----------------------------------------------------
__device__ __forceinline__ unsigned f2tf(float x){
  unsigned u; asm("cvt.rna.tf32.f32 %0, %1;" : "=r"(u) : "f"(x)); return u;
}
__device__ __forceinline__ void mma_tf32(float c[4], const unsigned a[4], const unsigned b[2]){
  asm volatile("mma.sync.aligned.m16n8k8.row.col.f32.tf32.tf32.f32 "
    "{%0,%1,%2,%3},{%4,%5,%6,%7},{%8,%9},{%0,%1,%2,%3};"
    : "+f"(c[0]),"+f"(c[1]),"+f"(c[2]),"+f"(c[3])
    : "r"(a[0]),"r"(a[1]),"r"(a[2]),"r"(a[3]),"r"(b[0]),"r"(b[1]));
}
__device__ __forceinline__ void ldsm4(unsigned r[4], uint32_t a){
  asm volatile("ldmatrix.sync.aligned.m8n8.x4.shared.b16 {%0,%1,%2,%3}, [%4];"
    : "=r"(r[0]),"=r"(r[1]),"=r"(r[2]),"=r"(r[3]) : "r"(a));
}
__device__ __forceinline__ uint32_t s2u(const void* p){
  uint32_t a; asm("{ .reg .u64 t; cvta.to.shared.u64 t, %1; cvt.u32.u64 %0, t; }" : "=r"(a) : "l"(p)); return a;
}
__device__ __forceinline__ void cpa16(uint32_t s, const void* g){
  asm volatile("cp.async.cg.shared.global [%0], [%1], 16;" :: "r"(s), "l"(g));
}
#define CPC() asm volatile("cp.async.commit_group;" ::: "memory")
#define CPW1() asm volatile("cp.async.wait_group 1;" ::: "memory")
#define CPW0() asm volatile("cp.async.wait_group 0;" ::: "memory")

__device__ __forceinline__ float warpSum(float v){
#pragma unroll
  for(int o=16;o;o>>=1) v += __shfl_xor_sync(0xffffffffu, v, o);
  return v;
}
__device__ __forceinline__ float warpMax(float v){
#pragma unroll
  for(int o=16;o;o>>=1) v = fmaxf(v, __shfl_xor_sync(0xffffffffu, v, o));
  return v;
}
__device__ __forceinline__ float blockSum(float v, float* red, int nw){
  int t=threadIdx.x; v=warpSum(v);
  if((t&31)==0) red[t>>5]=v;
  __syncthreads();
  float s=0.f;
  if(t<32){ s=(t<nw)?red[t]:0.f; s=warpSum(s); if(t==0) red[0]=s; }
  __syncthreads(); s=red[0]; __syncthreads(); return s;
}
__device__ __forceinline__ float blockMax(float v, float* red, int nw){
  int t=threadIdx.x; v=warpMax(v);
  if((t&31)==0) red[t>>5]=v;
  __syncthreads();
  float s=-3.4e38f;
  if(t<32){ s=(t<nw)?red[t]:-3.4e38f; s=warpMax(s); if(t==0) red[0]=s; }
  __syncthreads(); s=red[0]; __syncthreads(); return s;
}

// ---- prep: convert+transpose 6 weight mats to tf32 [mat][n][k] ---------------
__global__ void k_prep(const float* __restrict__ w0, const float* __restrict__ w1,
                       const float* __restrict__ w2, const float* __restrict__ w3,
                       const float* __restrict__ w4, const float* __restrict__ w5){
  int bid = blockIdx.x, t = threadIdx.x;
  int mat = bid>>8, n = bid&255;
  const float* W = (mat==0)?w0:(mat==1)?w1:(mat==2)?w2:(mat==3)?w3:(mat==4)?w4:w5;
  g_wt[(size_t)bid*256 + t] = f2tf(W[t*256 + n]);
}

// ---- K0: qsw row 0 -----------------------------------------------------------
__global__ void k_qsw(const float* __restrict__ msa, const float* __restrict__ lng,
                      const float* __restrict__ lnb, const float* __restrict__ swq,
                      const float* __restrict__ sbq){
  int i = blockIdx.x, t = threadIdx.x;
  __shared__ float sm[HD]; __shared__ float red[32];
  float x = msa[(size_t)i*HD + t];
  float mean = blockSum(x, red, 8)*(1.f/HD);
  float d = x-mean;
  float var = blockSum(d*d, red, 8)*(1.f/HD);
  sm[t] = d*rsqrtf(var+1e-5f)*lng[t]+lnb[t];
  __syncthreads();
  float acc = sbq[t];
#pragma unroll 8
  for(int r=0;r<HD;r++) acc += sm[r]*swq[r*HD+t];
  g_qsw[i*HD+t] = acc*ISD;
}

// ---- K3: pair LN + bias projection via MMA -----------------------------------
// per block: 128 pairs. A = LN(pair) [128 x 132pad tf32], B = wb [128k x 8h tf32]
#define PB_SMEM ((128*132 + 1024)*4)
__global__ __launch_bounds__(256) void k_pbmm(const float* __restrict__ pair,
    const float* __restrict__ lnpg, const float* __restrict__ lnpb,
    const float* __restrict__ wb){
  extern __shared__ unsigned dsm[];
  unsigned (*sA)[132] = (unsigned(*)[132])dsm;
  unsigned* swb = dsm + 128*132;
  const uint32_t sbA = s2u(dsm);
  const int t = threadIdx.x;
  const size_t p0 = (size_t)blockIdx.x*128;
  for(int u=t; u<1024; u+=256) swb[u] = f2tf(wb[u]);
  { // LN: 2 threads per pair-row
    int row = t>>1, half = t&1;
    const float* rp = pair + (p0+row)*128 + half*64;
    float s=0.f, ss=0.f;
#pragma unroll
    for(int f=0;f<16;f++){ float4 x = *(const float4*)(rp+f*4);
      s += x.x+x.y+x.z+x.w; ss += x.x*x.x+x.y*x.y+x.z*x.z+x.w*x.w; }
    s  += __shfl_xor_sync(0xffffffffu, s, 1);
    ss += __shfl_xor_sync(0xffffffffu, ss, 1);
    float mean = s*(1.f/128.f), inv = rsqrtf(ss*(1.f/128.f)-mean*mean+1e-5f);
#pragma unroll
    for(int f=0;f<16;f++){
      int c = half*64 + f*4;
      float4 x = *(const float4*)(pair + (p0+row)*128 + c);
      sA[row][c  ] = f2tf((x.x-mean)*inv*lnpg[c  ]+lnpb[c  ]);
      sA[row][c+1] = f2tf((x.y-mean)*inv*lnpg[c+1]+lnpb[c+1]);
      sA[row][c+2] = f2tf((x.z-mean)*inv*lnpg[c+2]+lnpb[c+2]);
      sA[row][c+3] = f2tf((x.w-mean)*inv*lnpg[c+3]+lnpb[c+3]);
    }
  }
  __syncthreads();
  const int w = t>>5, lane = t&31;
  const int qr = lane>>2, ql = lane&3;
  const int R = w*16;
  const uint32_t aoff = sbA + ((R + (lane&15))*132 + ((lane>>4)<<2))*4;
  float acc[4] = {0.f,0.f,0.f,0.f};
#pragma unroll
  for(int ks=0; ks<16; ks++){
    unsigned a[4], b[2];
    ldsm4(a, aoff + ks*32);
    b[0] = swb[(ks*8+ql  )*8 + qr];
    b[1] = swb[(ks*8+ql+4)*8 + qr];
    mma_tf32(acc, a, b);
  }
  size_t p = p0 + R + qr;
  int h0 = 2*ql, h1 = 2*ql+1;
  g_pb[(size_t)h0*LLc + p]     = acc[0];
  g_pb[(size_t)h1*LLc + p]     = acc[1];
  g_pb[(size_t)h0*LLc + p + 8] = acc[2];
  g_pb[(size_t)h1*LLc + p + 8] = acc[3];
}

// ---- K1: LN + 5 projections, ldmatrix + cp.async -----------------------------
#define PROJ_SMEM ((128*260 + 2*64*132)*4)
__global__ __launch_bounds__(256) void k_proj(const float* __restrict__ msa,
    const float* __restrict__ lng, const float* __restrict__ lnb,
    const float* __restrict__ sbk, const float* __restrict__ bg){
  extern __shared__ unsigned dsm[];
  unsigned (*sA)[260] = (unsigned(*)[260])dsm;
  unsigned* sB = dsm + 128*260;
  const uint32_t sbA = s2u(dsm), sbB = s2u(sB);
  __shared__ float smean[128], sinv[128];

  const int t = threadIdx.x;
  const size_t row0 = (size_t)blockIdx.x*128;
  const int nn = (int)(row0/Ll);
  const int ibase = (int)(row0%Ll);

  // prefetch tile 0 (mat0, sub0, kh0)
#pragma unroll
  for(int c=0;c<8;c++){
    int u = c*256 + t, n = u>>5, cu = u&31;
    cpa16(sbB + (n*132 + cu*4)*4, &g_wt[(size_t)n*256 + cu*4]);
  }
  CPC();
  { // LN stats: 2 threads/row
    int row = t>>1, q = t&1;
    const float* rp = msa + (row0+row)*HD + q*128;
    float s=0.f, ss=0.f;
#pragma unroll
    for(int f=0;f<32;f++){ float4 x = *(const float4*)(rp+f*4);
      s += x.x+x.y+x.z+x.w; ss += x.x*x.x+x.y*x.y+x.z*x.z+x.w*x.w; }
    s  += __shfl_xor_sync(0xffffffffu, s, 1);
    ss += __shfl_xor_sync(0xffffffffu, ss, 1);
    float mean = s*(1.f/HD), var = ss*(1.f/HD)-mean*mean;
    if(q==0){ smean[row]=mean; sinv[row]=rsqrtf(var+1e-5f); }
  }
  __syncthreads();
#pragma unroll
  for(int p=0;p<32;p++){
    int lin = p*256 + t, r = lin>>6, f = lin&63;
    float4 x = *(const float4*)(msa + (row0+r)*HD + f*4);
    float mean = smean[r], inv = sinv[r];
    int c = f*4;
    sA[r][c  ] = f2tf((x.x-mean)*inv*lng[c  ]+lnb[c  ]);
    sA[r][c+1] = f2tf((x.y-mean)*inv*lng[c+1]+lnb[c+1]);
    sA[r][c+2] = f2tf((x.z-mean)*inv*lng[c+2]+lnb[c+2]);
    sA[r][c+3] = f2tf((x.w-mean)*inv*lng[c+3]+lnb[c+3]);
  }

  const int w = t>>5, lane = t&31;
  const int wm = w>>1, wn = w&1;
  const int qr = lane>>2, ql = lane&3;
  const uint32_t aL0 = sbA + ((wm*32 + (lane&15))*260 + ((lane>>4)<<2))*4;
  const uint32_t aL1 = aL0 + 16*260*4;
  const uint32_t bLn = ((wn*32 + (lane&7) + ((lane&16)>>1))*132 + ((lane>>3)&1)*4)*4;
  float acc[2][4][4];

  for(int T=0; T<40; T++){
    const int nc = T>>1, kh = T&1, mi = nc>>2, sub = nc&3;
    if(T+1 < 40){
      int nc2 = (T+1)>>1, kh2 = (T+1)&1;
      const unsigned* src = g_wt + (size_t)(((nc2>>2)*256 + (nc2&3)*64)<<8) + kh2*128;
      uint32_t dst = sbB + (((T+1)&1)*8448)*4;
#pragma unroll
      for(int c=0;c<8;c++){
        int u = c*256 + t, n = u>>5, cu = u&31;
        cpa16(dst + (n*132 + cu*4)*4, src + ((size_t)n<<8) + cu*4);
      }
      CPC(); CPW1();
    } else CPW0();
    __syncthreads();

    if(kh==0){
#pragma unroll
      for(int am=0;am<2;am++)
#pragma unroll
        for(int bn=0;bn<4;bn++)
#pragma unroll
          for(int e=0;e<4;e++) acc[am][bn][e]=0.f;
    }
    const uint32_t bufB = sbB + (T&1)*8448*4;
    const uint32_t ahalf = kh*512;
#pragma unroll
    for(int ks=0; ks<16; ks++){
      const uint32_t kb = ks*32;
      unsigned a0[4], a1[4], bf0[4], bf1[4];
      ldsm4(a0, aL0 + ahalf + kb);
      ldsm4(a1, aL1 + ahalf + kb);
      ldsm4(bf0, bufB + bLn + kb);
      ldsm4(bf1, bufB + bLn + 16*132*4 + kb);
      mma_tf32(acc[0][0], a0, bf0);  mma_tf32(acc[0][1], a0, bf0+2);
      mma_tf32(acc[0][2], a0, bf1);  mma_tf32(acc[0][3], a0, bf1+2);
      mma_tf32(acc[1][0], a1, bf0);  mma_tf32(acc[1][1], a1, bf0+2);
      mma_tf32(acc[1][2], a1, bf1);  mma_tf32(acc[1][3], a1, bf1+2);
    }
    if(kh==1){
#pragma unroll
      for(int am=0;am<2;am++){
        int rloc = wm*32 + am*16 + qr;
        int rowa = (int)row0 + rloc;
#pragma unroll
        for(int bn=0;bn<4;bn++){
          int cg = sub*64 + wn*32 + bn*8 + 2*ql;
          size_t o0 = (size_t)rowa*HD + cg, o1 = o0 + 8*HD;
          float v0=acc[am][bn][0], v1=acc[am][bn][1], v2=acc[am][bn][2], v3=acc[am][bn][3];
          if(mi==0){
            float b0=sbk[cg], b1=sbk[cg+1];
            *(float2*)(g_ksw+o0)=make_float2(v0+b0,v1+b1);
            *(float2*)(g_ksw+o1)=make_float2(v2+b0,v3+b1);
          } else if(mi==1){
            *(float2*)(g_mq+o0)=make_float2(v0,v1);
            *(float2*)(g_mq+o1)=make_float2(v2,v3);
          } else if(mi==2){
            *(uint2*)(g_kt+o0)=make_uint2(f2tf(v0*ISD), f2tf(v1*ISD));
            *(uint2*)(g_kt+o1)=make_uint2(f2tf(v2*ISD), f2tf(v3*ISD));
          } else if(mi==3){
            int i = ibase + rloc;
            size_t d0 = ((size_t)(nn*8 + (cg>>5))*32 + (cg&31))*Ll + i;
            g_vT[d0]      = f2tf(v0);
            g_vT[d0+Ll]   = f2tf(v1);
            g_vT[d0+8]    = f2tf(v2);
            g_vT[d0+Ll+8] = f2tf(v3);
          } else {
            float b0=bg[cg], b1=bg[cg+1];
            *(float2*)(g_gate+o0)=make_float2(1.f/(1.f+expf(-(v0+b0))), 1.f/(1.f+expf(-(v1+b1))));
            *(float2*)(g_gate+o1)=make_float2(1.f/(1.f+expf(-(v2+b0))), 1.f/(1.f+expf(-(v3+b1))));
          }
        }
      }
    }
    __syncthreads();
  }
}

// ---- K2: seq-weight logits + softmax over n ----------------------------------
__global__ __launch_bounds__(256) void k_swl(){
  __shared__ float sq[256]; __shared__ float sL[256][9];
  __shared__ float smx[8], srs[8];
  int i = blockIdx.x, t = threadIdx.x;
  sq[t] = g_qsw[i*HD+t];
  __syncthreads();
  const float* kr = g_ksw + ((size_t)t*Ll + i)*HD;
  float lg[8];
#pragma unroll
  for(int h=0;h<8;h++){
    float s=0.f;
#pragma unroll
    for(int f=0;f<8;f++){
      float4 kx = *(const float4*)(kr + h*32 + f*4);
      int c = h*32+f*4;
      s += kx.x*sq[c]+kx.y*sq[c+1]+kx.z*sq[c+2]+kx.w*sq[c+3];
    }
    lg[h]=s; sL[t][h]=s;
  }
  __syncthreads();
  { int w=t>>5, lane=t&31;
    float mx=-3.4e38f;
#pragma unroll
    for(int e=0;e<8;e++) mx=fmaxf(mx, sL[lane*8+e][w]);
    mx=warpMax(mx);
    float s=0.f;
#pragma unroll
    for(int e=0;e<8;e++) s+=expf(sL[lane*8+e][w]-mx);
    s=warpSum(s);
    if(lane==0){ smx[w]=mx; srs[w]=1.f/s; } }
  __syncthreads();
  size_t o = ((size_t)t*Ll + i)*Hh;
#pragma unroll
  for(int h=0;h<8;h++) g_sw[o+h] = expf(lg[h]-smx[h])*srs[h];
}

// ---- K_qs: Q * seqweight -> tf32 ---------------------------------------------
__global__ __launch_bounds__(256) void k_qs(){
  int u = blockIdx.x*256 + threadIdx.x;
  int row = u>>6, c4 = (u&63)*4;
  float sv = g_sw[(size_t)row*Hh + (c4>>5)];
  float4 x = *(const float4*)(g_mq + (size_t)row*HD + c4);
  uint4 o;
  o.x=f2tf(x.x*sv); o.y=f2tf(x.y*sv); o.z=f2tf(x.z*sv); o.w=f2tf(x.w*sv);
  *(uint4*)(g_qst + (size_t)row*HD + c4) = o;
}

// ---- K4: attn logits, ldmatrix + cp.async ------------------------------------
#define ATTN_SMEM (2*6912*4)
__global__ __launch_bounds__(256) void k_attn(){
  extern __shared__ unsigned dsm[];
  const uint32_t sb = s2u(dsm);
  const int t = threadIdx.x, h = blockIdx.z, i0 = blockIdx.x*128, j0 = blockIdx.y*64;
  const int w = t>>5, lane = t&31;
  const int wm = w>>1, wn = w&1;
  const int qr = lane>>2, ql = lane&3;
  const uint32_t aLn = ((wm*32 + (lane&15))*36 + ((lane>>4)<<2))*4;
  const uint32_t bLn = ((wn*32 + (lane&7) + ((lane&16)>>1))*36 + ((lane>>3)&1)*4)*4;
  float acc[2][4][4];
#pragma unroll
  for(int am=0;am<2;am++)
#pragma unroll
    for(int bn=0;bn<4;bn++)
#pragma unroll
      for(int e=0;e<4;e++) acc[am][bn][e]=0.f;

#pragma unroll
  for(int c=0;c<4;c++){ int u=c*256+t, r=u>>3, cu=u&7;
    cpa16(sb + (r*36+cu*4)*4, &g_qst[((size_t)(i0+r))*HD + h*32 + cu*4]); }
#pragma unroll
  for(int c=0;c<2;c++){ int u=c*256+t, r=u>>3, cu=u&7;
    cpa16(sb + (4608+r*36+cu*4)*4, &g_kt[((size_t)(j0+r))*HD + h*32 + cu*4]); }
  CPC();
  for(int n=0;n<Nn;n++){
    if(n+1<Nn){
      uint32_t dst = sb + (((n+1)&1)*6912)*4;
      size_t rowA = (size_t)(n+1)*Ll + i0, rowB = (size_t)(n+1)*Ll + j0;
#pragma unroll
      for(int c=0;c<4;c++){ int u=c*256+t, r=u>>3, cu=u&7;
        cpa16(dst + (r*36+cu*4)*4, &g_qst[(rowA+r)*HD + h*32 + cu*4]); }
#pragma unroll
      for(int c=0;c<2;c++){ int u=c*256+t, r=u>>3, cu=u&7;
        cpa16(dst + (4608+r*36+cu*4)*4, &g_kt[(rowB+r)*HD + h*32 + cu*4]); }
      CPC(); CPW1();
    } else CPW0();
    __syncthreads();
    const uint32_t st = sb + (n&1)*6912*4;
    const uint32_t bst = st + 4608*4;
#pragma unroll
    for(int ks=0;ks<4;ks++){
      const uint32_t kb = ks*32;
      unsigned a0[4], a1[4], bf0[4], bf1[4];
      ldsm4(a0, st + aLn + kb);
      ldsm4(a1, st + aLn + 16*36*4 + kb);
      ldsm4(bf0, bst + bLn + kb);
      ldsm4(bf1, bst + bLn + 16*36*4 + kb);
      mma_tf32(acc[0][0], a0, bf0);  mma_tf32(acc[0][1], a0, bf0+2);
      mma_tf32(acc[0][2], a0, bf1);  mma_tf32(acc[0][3], a0, bf1+2);
      mma_tf32(acc[1][0], a1, bf0);  mma_tf32(acc[1][1], a1, bf0+2);
      mma_tf32(acc[1][2], a1, bf1);  mma_tf32(acc[1][3], a1, bf1+2);
    }
    __syncthreads();
  }
  const size_t hb = (size_t)h*LLc;
#pragma unroll
  for(int am=0;am<2;am++){
    int i = i0 + wm*32 + am*16 + qr;
#pragma unroll
    for(int bn=0;bn<4;bn++){
      int j = j0 + wn*32 + bn*8 + 2*ql;
      size_t o = hb + (size_t)i*Ll + j;
      float2 pb0 = *(const float2*)(g_pb+o);
      *(float2*)(g_attn+o) = make_float2(acc[am][bn][0]+pb0.x, acc[am][bn][1]+pb0.y);
      size_t o2 = o + (size_t)8*Ll;
      float2 pb1 = *(const float2*)(g_pb+o2);
      *(float2*)(g_attn+o2) = make_float2(acc[am][bn][2]+pb1.x, acc[am][bn][3]+pb1.y);
    }
  }
}

// ---- K5: softmax over j -> tf32 probs ----------------------------------------
__global__ void k_attnsoftmax(){
  int b = blockIdx.x, h = b/Ll, i = b%Ll, t = threadIdx.x;
  __shared__ float red[32];
  size_t base = (size_t)h*LLc + (size_t)i*Ll;
  float x0 = g_attn[base+t], x1 = g_attn[base+128+t], x2 = g_attn[base+256+t];
  float mx = blockMax(fmaxf(x0,fmaxf(x1,x2)), red, 4);
  float e0=expf(x0-mx), e1=expf(x1-mx), e2=expf(x2-mx);
  float s = blockSum(e0+e1+e2, red, 4);
  float inv = 1.f/s;
  g_pt[base+t]     = f2tf(e0*inv);
  g_pt[base+128+t] = f2tf(e1*inv);
  g_pt[base+256+t] = f2tf(e2*inv);
}

// ---- K6: P @ V, ldmatrix + cp.async ------------------------------------------
#define PV_SMEM (2*9216*4)
__global__ __launch_bounds__(256) void k_pv(){
  extern __shared__ unsigned dsm[];
  const uint32_t sb = s2u(dsm);
  const int t = threadIdx.x, h = blockIdx.z, i0 = blockIdx.x*128, n0 = blockIdx.y*4;
  const int w = t>>5, lane = t&31;
  const int wm = w>>1, wn = w&1;
  const int qr = lane>>2, ql = lane&3;
  const uint32_t aLn = ((wm*32 + (lane&15))*36 + ((lane>>4)<<2))*4;
  const uint32_t bLn = ((wn*64 + (lane&7) + ((lane&16)>>1))*36 + ((lane>>3)&1)*4)*4;
  float acc[2][8][4];
#pragma unroll
  for(int am=0;am<2;am++)
#pragma unroll
    for(int bn=0;bn<8;bn++)
#pragma unroll
      for(int e=0;e<4;e++) acc[am][bn][e]=0.f;

  const size_t aBase = (size_t)h*LLc + (size_t)i0*Ll;
#pragma unroll
  for(int c=0;c<4;c++){ int u=c*256+t, r=u>>3, cu=u&7;
    cpa16(sb + (r*36+cu*4)*4, &g_pt[aBase + (size_t)r*Ll + cu*4]); }
#pragma unroll
  for(int c=0;c<4;c++){ int u=c*256+t, rr=u>>3, cu=u&7;
    size_t grow = ((size_t)(n0+(rr>>5))*8 + h)*32 + (rr&31);
    cpa16(sb + (4608+rr*36+cu*4)*4, &g_vT[grow*Ll + cu*4]); }
  CPC();
  for(int jc=0;jc<12;jc++){
    if(jc+1<12){
      int j1 = (jc+1)*32;
      uint32_t dst = sb + (((jc+1)&1)*9216)*4;
#pragma unroll
      for(int c=0;c<4;c++){ int u=c*256+t, r=u>>3, cu=u&7;
        cpa16(dst + (r*36+cu*4)*4, &g_pt[aBase + (size_t)r*Ll + j1 + cu*4]); }
#pragma unroll
      for(int c=0;c<4;c++){ int u=c*256+t, rr=u>>3, cu=u&7;
        size_t grow = ((size_t)(n0+(rr>>5))*8 + h)*32 + (rr&31);
        cpa16(dst + (4608+rr*36+cu*4)*4, &g_vT[grow*Ll + j1 + cu*4]); }
      CPC(); CPW1();
    } else CPW0();
    __syncthreads();
    const uint32_t st = sb + (jc&1)*9216*4;
    const uint32_t bst = st + 4608*4;
#pragma unroll
    for(int ks=0;ks<4;ks++){
      const uint32_t kb = ks*32;
      unsigned a0[4], a1[4], bf[4][4];
      ldsm4(a0, st + aLn + kb);
      ldsm4(a1, st + aLn + 16*36*4 + kb);
#pragma unroll
      for(int q=0;q<4;q++) ldsm4(bf[q], bst + bLn + q*16*36*4 + kb);
#pragma unroll
      for(int bn=0;bn<8;bn++){
        mma_tf32(acc[0][bn], a0, bf[bn>>1] + 2*(bn&1));
        mma_tf32(acc[1][bn], a1, bf[bn>>1] + 2*(bn&1));
      }
    }
    __syncthreads();
  }
#pragma unroll
  for(int am=0;am<2;am++){
    int i = i0 + wm*32 + am*16 + qr;
#pragma unroll
    for(int bn=0;bn<8;bn++){
      int col = wn*64 + bn*8 + 2*ql;
      int nv = col>>5, dd = col&31;
      size_t o = ((size_t)(n0+nv)*Ll + i)*HD + h*Dd + dd;
      *(float2*)(g_oatt+o) = make_float2(acc[am][bn][0], acc[am][bn][1]);
      size_t o2 = o + (size_t)8*HD;
      *(float2*)(g_oatt+o2) = make_float2(acc[am][bn][2], acc[am][bn][3]);
    }
  }
}

// ---- K7: gate + out projection, ldmatrix + cp.async --------------------------
__global__ __launch_bounds__(256) void k_out(const float* __restrict__ bo,
                                             float* __restrict__ out){
  extern __shared__ unsigned dsm[];
  unsigned (*sA)[260] = (unsigned(*)[260])dsm;
  unsigned* sB = dsm + 128*260;
  const uint32_t sbA = s2u(dsm), sbB = s2u(sB);
  const int t = threadIdx.x;
  const size_t row0 = (size_t)blockIdx.x*128;
  const int w = t>>5, lane = t&31;
  const int wm = w>>1, wn = w&1;
  const int qr = lane>>2, ql = lane&3;

#pragma unroll
  for(int c=0;c<8;c++){
    int u = c*256 + t, n = u>>5, cu = u&31;
    cpa16(sbB + (n*132 + cu*4)*4, &g_wt[(size_t)(5*256 + n)*256 + cu*4]);
  }
  CPC();
#pragma unroll
  for(int p=0;p<32;p++){
    int lin = p*256 + t, r = lin>>6, f = lin&63;
    size_t o = (row0+r)*HD + f*4;
    float4 a = *(const float4*)(g_oatt+o);
    float4 g = *(const float4*)(g_gate+o);
    int c = f*4;
    sA[r][c]=f2tf(a.x*g.x); sA[r][c+1]=f2tf(a.y*g.y);
    sA[r][c+2]=f2tf(a.z*g.z); sA[r][c+3]=f2tf(a.w*g.w);
  }
  const uint32_t aL0 = sbA + ((wm*32 + (lane&15))*260 + ((lane>>4)<<2))*4;
  const uint32_t aL1 = aL0 + 16*260*4;
  const uint32_t bLn = ((wn*32 + (lane&7) + ((lane&16)>>1))*132 + ((lane>>3)&1)*4)*4;
  float acc[2][4][4];
  for(int T=0;T<8;T++){
    const int nc = T>>1, kh = T&1;
    if(T+1<8){
      int nc2=(T+1)>>1, kh2=(T+1)&1;
      const unsigned* src = g_wt + (size_t)(5*256 + nc2*64)*256 + kh2*128;
      uint32_t dst = sbB + (((T+1)&1)*8448)*4;
#pragma unroll
      for(int c=0;c<8;c++){
        int u = c*256 + t, n = u>>5, cu = u&31;
        cpa16(dst + (n*132 + cu*4)*4, src + ((size_t)n<<8) + cu*4);
      }
      CPC(); CPW1();
    } else CPW0();
    __syncthreads();
    if(kh==0){
#pragma unroll
      for(int am=0;am<2;am++)
#pragma unroll
        for(int bn=0;bn<4;bn++)
#pragma unroll
          for(int e=0;e<4;e++) acc[am][bn][e]=0.f;
    }
    const uint32_t bufB = sbB + (T&1)*8448*4;
    const uint32_t ahalf = kh*512;
#pragma unroll
    for(int ks=0;ks<16;ks++){
      const uint32_t kb = ks*32;
      unsigned a0[4], a1[4], bf0[4], bf1[4];
      ldsm4(a0, aL0 + ahalf + kb);
      ldsm4(a1, aL1 + ahalf + kb);
      ldsm4(bf0, bufB + bLn + kb);
      ldsm4(bf1, bufB + bLn + 16*132*4 + kb);
      mma_tf32(acc[0][0], a0, bf0);  mma_tf32(acc[0][1], a0, bf0+2);
      mma_tf32(acc[0][2], a0, bf1);  mma_tf32(acc[0][3], a0, bf1+2);
      mma_tf32(acc[1][0], a1, bf0);  mma_tf32(acc[1][1], a1, bf0+2);
      mma_tf32(acc[1][2], a1, bf1);  mma_tf32(acc[1][3], a1, bf1+2);
    }
    if(kh==1){
#pragma unroll
      for(int am=0;am<2;am++){
        int rowa = (int)row0 + wm*32 + am*16 + qr;
#pragma unroll
        for(int bn=0;bn<4;bn++){
          int cg = nc*64 + wn*32 + bn*8 + 2*ql;
          float2 b2 = *(const float2*)(bo + cg);
          *(float2*)(out + (size_t)rowa*HD + cg) = make_float2(acc[am][bn][0]+b2.x, acc[am][bn][1]+b2.y);
          *(float2*)(out + (size_t)(rowa+8)*HD + cg) = make_float2(acc[am][bn][2]+b2.x, acc[am][bn][3]+b2.y);
        }
      }
    }
    __syncthreads();
  }
}

// ---- launch ------------------------------------------------------------------
extern "C" void kernel_launch(void* const* d_in, const int* in_sizes, int n_in,
                              void* d_out, int out_size){
  const float* msa      = (const float*)d_in[0];
  const float* pair     = (const float*)d_in[1];
  const float* ln_msa_g = (const float*)d_in[2];
  const float* ln_msa_b = (const float*)d_in[3];
  const float* ln_pair_g= (const float*)d_in[4];
  const float* ln_pair_b= (const float*)d_in[5];
  const float* sw_wq    = (const float*)d_in[6];
  const float* sw_bq    = (const float*)d_in[7];
  const float* sw_wk    = (const float*)d_in[8];
  const float* sw_bk    = (const float*)d_in[9];
  const float* wq       = (const float*)d_in[10];
  const float* wk       = (const float*)d_in[11];
  const float* wv       = (const float*)d_in[12];
  const float* wb       = (const float*)d_in[13];
  const float* wg       = (const float*)d_in[14];
  const float* bg       = (const float*)d_in[15];
  const float* wo       = (const float*)d_in[16];
  const float* bo       = (const float*)d_in[17];
  float* out = (float*)d_out;

  cudaFuncSetAttribute(k_proj, cudaFuncAttributeMaxDynamicSharedMemorySize, PROJ_SMEM);
  cudaFuncSetAttribute(k_attn, cudaFuncAttributeMaxDynamicSharedMemorySize, ATTN_SMEM);
  cudaFuncSetAttribute(k_pv,   cudaFuncAttributeMaxDynamicSharedMemorySize, PV_SMEM);
  cudaFuncSetAttribute(k_out,  cudaFuncAttributeMaxDynamicSharedMemorySize, PROJ_SMEM);
  cudaFuncSetAttribute(k_pbmm, cudaFuncAttributeMaxDynamicSharedMemorySize, PB_SMEM);

  k_prep<<<6*256, 256>>>(sw_wk, wq, wk, wv, wg, wo);          // 1
  k_qsw<<<Ll, 256>>>(msa, ln_msa_g, ln_msa_b, sw_wq, sw_bq);  // 2
  k_pbmm<<<LLc/128, 256, PB_SMEM>>>(pair, ln_pair_g, ln_pair_b, wb); // 3
  k_proj<<<NL/128, 256, PROJ_SMEM>>>(msa, ln_msa_g, ln_msa_b, sw_bk, bg); // 4 (ncu slot)
  k_swl<<<Ll, 256>>>();                                       // 5
  k_qs<<<NL*HD/1024, 256>>>();                                // 6
  k_attn<<<dim3(3,6,8), 256, ATTN_SMEM>>>();                  // 7
  k_attnsoftmax<<<Hh*Ll, 128>>>();                            // 8
  k_pv<<<dim3(3,64,8), 256, PV_SMEM>>>();                     // 9
  k_out<<<NL/128, 256, PROJ_SMEM>>>(bo, out);                 // 10
}